// round 7
// baseline (speedup 1.0000x reference)
#include <cuda_runtime.h>
#include <cuda_fp16.h>
#include <math.h>

#define NN 100000
#define EE 1600000
#define EPAD (EE + 8 * NN)
#define HID 64
#define KORD 14
#define HEADS 8
#define NGRAPH 128
#define NCLS 10

// ---------------- scratch (device globals; no runtime alloc) ----------------
// Chebyshev T buffers: int8 rows (64B = 8 int2 per node) + per-node half scale
__device__ int2   g_q0[NN * 8];
__device__ int2   g_q1[NN * 8];
__device__ int2   g_q2[NN * 8];
__device__ __half g_s0[NN];
__device__ __half g_s1[NN];
__device__ __half g_s2[NN];
__device__ __half g_outh[NN * HID];   // fp16 accumulator of sum_k c_k T_k
__device__ float  g_h   [NN * HID];   // fp32 layer output
__device__ int    g_deg[NN];
__device__ float  g_dinv[NN];
__device__ int    g_rowptr[NN + 1];   // padded prefix (multiples of 8)
__device__ int    g_cursor[NN];
__device__ int2   g_edge[EPAD];       // {col, float_bits(weight)}, zero-weight padding
__device__ float  g_coeff[3][KORD];

// ---------------- init ----------------
__global__ void init_kernel() {
    int i = blockIdx.x * blockDim.x + threadIdx.x;
    if (i < NN) { g_deg[i] = 0; g_cursor[i] = 0; }
}

__global__ void count_deg_kernel(const int* __restrict__ row) {
    int e = blockIdx.x * blockDim.x + threadIdx.x;
    if (e < EE) atomicAdd(&g_deg[row[e]], 1);
}

// scan (padded degrees) + dinv + coeff fused (single block)
__global__ void scan_kernel(const float* __restrict__ theta1,
                            const float* __restrict__ thetas) {
    __shared__ int sums[1024];
    const int T = 1024;
    int tid = threadIdx.x;

    if (tid < 3 * KORD) {
        int layer = tid / KORD, k = tid % KORD;
        const float* th = (layer == 0) ? theta1 : thetas + (layer - 1) * HEADS * KORD;
        float s = 0.f;
        for (int h = 0; h < HEADS; h++) s += th[h * KORD + k];
        g_coeff[layer][k] = s * (1.0f / HEADS);
    }

    int per = (NN + T - 1) / T;
    int start = tid * per;
    int end = start + per; if (end > NN) end = NN;
    int local = 0;
    for (int i = start; i < end; i++) local += (g_deg[i] + 7) & ~7;
    sums[tid] = local;
    __syncthreads();
    for (int off = 1; off < T; off <<= 1) {
        int t = (tid >= off) ? sums[tid - off] : 0;
        __syncthreads();
        sums[tid] += t;
        __syncthreads();
    }
    int excl = sums[tid] - local;
    int run = excl;
    for (int i = start; i < end; i++) {
        int d = g_deg[i];
        g_rowptr[i] = run; run += (d + 7) & ~7;
        g_dinv[i] = rsqrtf(fmaxf((float)d, 1.0f));
    }
    if (tid == T - 1) g_rowptr[NN] = run;
}

__global__ void scatter_kernel(const int* __restrict__ row, const int* __restrict__ col) {
    int e = blockIdx.x * blockDim.x + threadIdx.x;
    if (e < EE) {
        int r = row[e], c = col[e];
        int pos = g_rowptr[r] + atomicAdd(&g_cursor[r], 1);
        float w = -g_dinv[r] * g_dinv[c];
        g_edge[pos] = make_int2(c, __float_as_int(w));
    }
}

__global__ void pad_fill_kernel() {
    int r = blockIdx.x * blockDim.x + threadIdx.x;
    if (r < NN) {
        int s = g_rowptr[r] + g_deg[r];
        int e = g_rowptr[r + 1];
        for (int i = s; i < e; i++) g_edge[i] = make_int2(0, 0);
    }
}

// ---------------- quantization helpers ----------------
// pack 4 floats -> 4 int8 in an int, given inverse scale
__device__ __forceinline__ int qpack4(float a, float b, float c, float d, float inv) {
    int qa = __float2int_rn(a * inv);
    int qb = __float2int_rn(b * inv);
    int qc = __float2int_rn(c * inv);
    int qd = __float2int_rn(d * inv);
    return (qa & 255) | ((qb & 255) << 8) | ((qc & 255) << 16) | (qd << 24);
}

// ---------------- GEMM: Y[N][64] = A[N][FIN] @ W[FIN][64] -> int8 rows + scale ----------------
template <int FIN>
__global__ __launch_bounds__(256) void gemm_kernel(const float* __restrict__ A,
                                                   const float* __restrict__ W,
                                                   int* __restrict__ Yq,      // int[NN*16]
                                                   __half* __restrict__ Ys) {
    __shared__ float As[64][68];
    __shared__ float Ws[64][64];
    int rowbase = blockIdx.x * 64;
    int tid = threadIdx.x;
    int tx = tid & 15;
    int ty = tid >> 4;
    float acc[4][4];
#pragma unroll
    for (int i = 0; i < 4; i++)
#pragma unroll
        for (int j = 0; j < 4; j++) acc[i][j] = 0.f;

    for (int kk = 0; kk < FIN; kk += 64) {
#pragma unroll
        for (int j = 0; j < 4; j++) {
            int idx = tid + j * 256;
            int r = idx >> 4;
            int kq = idx & 15;
            float4 v = make_float4(0.f, 0.f, 0.f, 0.f);
            int gr = rowbase + r;
            if (gr < NN) v = *(const float4*)(A + (size_t)gr * FIN + kk + kq * 4);
            As[kq * 4 + 0][r] = v.x;
            As[kq * 4 + 1][r] = v.y;
            As[kq * 4 + 2][r] = v.z;
            As[kq * 4 + 3][r] = v.w;
        }
#pragma unroll
        for (int j = 0; j < 4; j++) {
            int idx = tid + j * 256;
            int k = idx >> 4;
            int fq = idx & 15;
            *(float4*)&Ws[k][fq * 4] = *(const float4*)(W + (size_t)(kk + k) * 64 + fq * 4);
        }
        __syncthreads();
#pragma unroll
        for (int k = 0; k < 64; k++) {
            float4 a = *(const float4*)&As[k][ty * 4];
            float4 b = *(const float4*)&Ws[k][tx * 4];
            float ar[4] = {a.x, a.y, a.z, a.w};
            float br[4] = {b.x, b.y, b.z, b.w};
#pragma unroll
            for (int i = 0; i < 4; i++)
#pragma unroll
                for (int j = 0; j < 4; j++) acc[i][j] += ar[i] * br[j];
        }
        __syncthreads();
    }
    // quantized epilogue: 16-lane row max, unconditional shuffles, predicated stores
#pragma unroll
    for (int i = 0; i < 4; i++) {
        int r = rowbase + ty * 4 + i;
        float m = fmaxf(fmaxf(fabsf(acc[i][0]), fabsf(acc[i][1])),
                        fmaxf(fabsf(acc[i][2]), fabsf(acc[i][3])));
#pragma unroll
        for (int off = 8; off; off >>= 1)
            m = fmaxf(m, __shfl_xor_sync(0xffffffffu, m, off, 16));
        float inv = (m > 0.f) ? 127.f / m : 0.f;
        int pk = qpack4(acc[i][0], acc[i][1], acc[i][2], acc[i][3], inv);
        if (r < NN) {
            Yq[(size_t)r * 16 + tx] = pk;
            if (tx == 0) Ys[r] = __float2half(m * (1.f / 127.f));
        }
    }
}

// ---------------- int8 Chebyshev propagation: 8-lane group, 8 int8 features/lane ----------------
// Branch-free 8-edge chunks; weights pre-multiplied by source scale per chunk.
__device__ __forceinline__ void prop8q(const int2* __restrict__ q,
                                       const __half* __restrict__ s,
                                       int st, int en, int sub, unsigned mask,
                                       float* __restrict__ acc) {
    const int2* qp = q + sub;
#pragma unroll
    for (int i = 0; i < 8; i++) acc[i] = 0.f;
    for (int base = st; base < en; base += 8) {
        int2 ew = __ldcg(&g_edge[base + sub]);
        // fold source scale into weight once per edge (scale array stays L1-hot via ldg)
        float wf = __int_as_float(ew.y) * __half2float(__ldg(&s[ew.x]));
        int2 raw[8];
#pragma unroll
        for (int j = 0; j < 8; j++) {
            int cj = __shfl_sync(mask, ew.x, j, 8);
            raw[j] = __ldcg(&qp[(size_t)cj * 8]);
        }
#pragma unroll
        for (int j = 0; j < 8; j++) {
            float wj = __shfl_sync(mask, wf, j, 8);
            int a = raw[j].x, b = raw[j].y;
            acc[0] += wj * (float)(signed char)(a);
            acc[1] += wj * (float)(signed char)(a >> 8);
            acc[2] += wj * (float)(signed char)(a >> 16);
            acc[3] += wj * (float)(a >> 24);
            acc[4] += wj * (float)(signed char)(b);
            acc[5] += wj * (float)(signed char)(b >> 8);
            acc[6] += wj * (float)(signed char)(b >> 16);
            acc[7] += wj * (float)(b >> 24);
        }
    }
}

// quantize 8 values of a row (8-lane group reduce) and store int2 + scale
__device__ __forceinline__ void quant_store8(const float* v, int2* __restrict__ qb,
                                             __half* __restrict__ sb,
                                             int row, int sub, unsigned mask) {
    float m = 0.f;
#pragma unroll
    for (int i = 0; i < 8; i++) m = fmaxf(m, fabsf(v[i]));
#pragma unroll
    for (int off = 4; off; off >>= 1) m = fmaxf(m, __shfl_xor_sync(mask, m, off, 8));
    float inv = (m > 0.f) ? 127.f / m : 0.f;
    int2 pk;
    pk.x = qpack4(v[0], v[1], v[2], v[3], inv);
    pk.y = qpack4(v[4], v[5], v[6], v[7], inv);
    qb[(size_t)row * 8 + sub] = pk;
    if (sub == 0) sb[row] = __float2half(m * (1.f / 127.f));
}

__device__ __forceinline__ void dequant8(int2 raw, float sc, float* v) {
    v[0] = sc * (float)(signed char)(raw.x);
    v[1] = sc * (float)(signed char)(raw.x >> 8);
    v[2] = sc * (float)(signed char)(raw.x >> 16);
    v[3] = sc * (float)(raw.x >> 24);
    v[4] = sc * (float)(signed char)(raw.y);
    v[5] = sc * (float)(signed char)(raw.y >> 8);
    v[6] = sc * (float)(signed char)(raw.y >> 16);
    v[7] = sc * (float)(raw.y >> 24);
}

__device__ __forceinline__ int4 packh8(const float* v) {
    __half2 h0 = __floats2half2_rn(v[0], v[1]);
    __half2 h1 = __floats2half2_rn(v[2], v[3]);
    __half2 h2 = __floats2half2_rn(v[4], v[5]);
    __half2 h3 = __floats2half2_rn(v[6], v[7]);
    int4 r;
    r.x = *(int*)&h0; r.y = *(int*)&h1;
    r.z = *(int*)&h2; r.w = *(int*)&h3;
    return r;
}

__device__ __forceinline__ void unpackh8(int4 raw, float* v) {
    const __half2* h = (const __half2*)&raw;
    float2 f0 = __half22float2(h[0]);
    float2 f1 = __half22float2(h[1]);
    float2 f2 = __half22float2(h[2]);
    float2 f3 = __half22float2(h[3]);
    v[0] = f0.x; v[1] = f0.y; v[2] = f1.x; v[3] = f1.y;
    v[4] = f2.x; v[5] = f2.y; v[6] = f3.x; v[7] = f3.y;
}

// first: t_cur = L~ y ; out = c0*y + c1*t_cur
__global__ __launch_bounds__(256) void cheb_first_kernel(const int2* __restrict__ qy,
                                                         const __half* __restrict__ sy,
                                                         int2* __restrict__ qt,
                                                         __half* __restrict__ st,
                                                         __half* __restrict__ outb,
                                                         int layer) {
    int lane = threadIdx.x & 31;
    int sub = lane & 7;
    int row = blockIdx.x * 32 + (threadIdx.x >> 3);
    if (row >= NN) return;
    unsigned mask = 0xFFu << (lane & 24);
    int s = g_rowptr[row], e = g_rowptr[row + 1];
    float acc[8];
    prop8q(qy, sy, s, e, sub, mask, acc);
    float c0 = g_coeff[layer][0], c1 = g_coeff[layer][1];
    size_t idx = (size_t)row * 8 + sub;
    float yv[8];
    dequant8(qy[idx], __half2float(sy[row]), yv);
    quant_store8(acc, qt, st, row, sub, mask);
    float ov[8];
#pragma unroll
    for (int i = 0; i < 8; i++) ov[i] = c0 * yv[i] + c1 * acc[i];
    ((int4*)outb)[idx] = packh8(ov);
}

// step k: t_next = 2*L~ t_cur - t_prev ; out += c_k * t_next
__global__ __launch_bounds__(256) void cheb_step_kernel(const int2* __restrict__ qc,
                                                        const __half* __restrict__ sc,
                                                        const int2* __restrict__ qp,
                                                        const __half* __restrict__ sp,
                                                        int2* __restrict__ qn,
                                                        __half* __restrict__ sn,
                                                        __half* __restrict__ outb,
                                                        int layer, int k) {
    int lane = threadIdx.x & 31;
    int sub = lane & 7;
    int row = blockIdx.x * 32 + (threadIdx.x >> 3);
    if (row >= NN) return;
    unsigned mask = 0xFFu << (lane & 24);
    int s = g_rowptr[row], e = g_rowptr[row + 1];
    float acc[8];
    prop8q(qc, sc, s, e, sub, mask, acc);
    size_t idx = (size_t)row * 8 + sub;
    float p[8], tn[8], o[8];
    dequant8(qp[idx], __half2float(sp[row]), p);
#pragma unroll
    for (int i = 0; i < 8; i++) tn[i] = 2.f * acc[i] - p[i];
    quant_store8(tn, qn, sn, row, sub, mask);
    float ck = g_coeff[layer][k];
    unpackh8(((int4*)outb)[idx], o);
#pragma unroll
    for (int i = 0; i < 8; i++) o[i] += ck * tn[i];
    ((int4*)outb)[idx] = packh8(o);
}

// last step: h_out = relu(out + c_k*(2*L~ t_cur - t_prev) + bias)  (fp32 output)
__global__ __launch_bounds__(256) void cheb_last_kernel(const int2* __restrict__ qc,
                                                        const __half* __restrict__ sc,
                                                        const int2* __restrict__ qp,
                                                        const __half* __restrict__ sp,
                                                        const __half* __restrict__ outb,
                                                        const float* __restrict__ bias,
                                                        float* __restrict__ hout,
                                                        int layer, int k) {
    int lane = threadIdx.x & 31;
    int sub = lane & 7;
    int row = blockIdx.x * 32 + (threadIdx.x >> 3);
    if (row >= NN) return;
    unsigned mask = 0xFFu << (lane & 24);
    int s = g_rowptr[row], e = g_rowptr[row + 1];
    float acc[8];
    prop8q(qc, sc, s, e, sub, mask, acc);
    size_t idx = (size_t)row * 8 + sub;
    float p[8], o[8];
    dequant8(qp[idx], __half2float(sp[row]), p);
    unpackh8(((const int4*)outb)[idx], o);
    float ck = g_coeff[layer][k];
    float4 b0 = *(const float4*)(bias + sub * 8);
    float4 b1 = *(const float4*)(bias + sub * 8 + 4);
    float bb[8] = {b0.x, b0.y, b0.z, b0.w, b1.x, b1.y, b1.z, b1.w};
    float r[8];
#pragma unroll
    for (int i = 0; i < 8; i++) {
        float tni = 2.f * acc[i] - p[i];
        r[i] = fmaxf(o[i] + ck * tni + bb[i], 0.f);
    }
    float* dst = hout + (size_t)row * HID + sub * 8;
    *(float4*)dst = make_float4(r[0], r[1], r[2], r[3]);
    *(float4*)(dst + 4) = make_float4(r[4], r[5], r[6], r[7]);
}

// ---------------- pool + head + log_softmax ----------------
__global__ __launch_bounds__(256) void pool_head_kernel(const float* __restrict__ h,
                                                        const int* __restrict__ batch,
                                                        const float* __restrict__ lin1w,
                                                        const float* __restrict__ lin1b,
                                                        const float* __restrict__ lin2w,
                                                        const float* __restrict__ lin2b,
                                                        float* __restrict__ out) {
    int g = blockIdx.x;
    int tid = threadIdx.x;
    int lo = 0, hi = NN;
    while (lo < hi) { int m = (lo + hi) >> 1; if (batch[m] < g) lo = m + 1; else hi = m; }
    int start = lo;
    lo = start; hi = NN;
    while (lo < hi) { int m = (lo + hi) >> 1; if (batch[m] < g + 1) lo = m + 1; else hi = m; }
    int end = lo;

    int f = tid & 63, sub = tid >> 6;
    float acc = 0.f;
    for (int i = start + sub; i < end; i += 4) acc += h[(size_t)i * HID + f];
    __shared__ float red[4][64];
    red[sub][f] = acc;
    __syncthreads();
    __shared__ float pooled[64];
    if (tid < 64) {
        float s = red[0][tid] + red[1][tid] + red[2][tid] + red[3][tid];
        float cnt = (float)(end - start);
        pooled[tid] = s / fmaxf(cnt, 1.0f);
    }
    __syncthreads();
    __shared__ float g1[64];
    if (tid < 64) {
        float a = lin1b[tid];
        for (int fk = 0; fk < 64; fk++) a += pooled[fk] * lin1w[fk * 64 + tid];
        g1[tid] = fmaxf(a, 0.f);
    }
    __syncthreads();
    __shared__ float logits[NCLS];
    if (tid < NCLS) {
        float a = lin2b[tid];
        for (int fk = 0; fk < 64; fk++) a += g1[fk] * lin2w[fk * NCLS + tid];
        logits[tid] = a;
    }
    __syncthreads();
    __shared__ float s_lse;
    if (tid == 0) {
        float mx = logits[0];
        for (int c = 1; c < NCLS; c++) mx = fmaxf(mx, logits[c]);
        float s = 0.f;
        for (int c = 0; c < NCLS; c++) s += expf(logits[c] - mx);
        s_lse = mx + logf(s);
    }
    __syncthreads();
    if (tid < NCLS) out[g * NCLS + tid] = logits[tid] - s_lse;
}

// ---------------- host orchestration ----------------
struct QBuf { int2* q; __half* s; };

static void spectral_layer(const float* hin, int fin, int layer,
                           const float* W, const float* bias,
                           QBuf b0, QBuf b1, QBuf b2,
                           __half* p_outh, float* hout) {
    const int CHEB_GRID = (NN + 31) / 32;
    if (fin == 128)
        gemm_kernel<128><<<(NN + 63) / 64, 256>>>(hin, W, (int*)b0.q, b0.s);
    else
        gemm_kernel<64><<<(NN + 63) / 64, 256>>>(hin, W, (int*)b0.q, b0.s);
    cheb_first_kernel<<<CHEB_GRID, 256>>>(b0.q, b0.s, b1.q, b1.s, p_outh, layer);
    QBuf tp = b0, tc = b1, tn = b2;
    for (int k = 2; k <= KORD - 2; k++) {
        cheb_step_kernel<<<CHEB_GRID, 256>>>(tc.q, tc.s, tp.q, tp.s, tn.q, tn.s,
                                             p_outh, layer, k);
        QBuf tmp = tp; tp = tc; tc = tn; tn = tmp;
    }
    cheb_last_kernel<<<CHEB_GRID, 256>>>(tc.q, tc.s, tp.q, tp.s, p_outh, bias,
                                         hout, layer, KORD - 1);
}

extern "C" void kernel_launch(void* const* d_in, const int* in_sizes, int n_in,
                              void* d_out, int out_size) {
    const float* x      = (const float*)d_in[0];
    const int*   ei     = (const int*)d_in[1];
    const int*   batch  = (const int*)d_in[2];
    const float* W1     = (const float*)d_in[3];
    const float* theta1 = (const float*)d_in[4];
    const float* b1     = (const float*)d_in[5];
    const float* Ws     = (const float*)d_in[6];
    const float* thetas = (const float*)d_in[7];
    const float* bs     = (const float*)d_in[8];
    const float* lin1w  = (const float*)d_in[9];
    const float* lin1b  = (const float*)d_in[10];
    const float* lin2w  = (const float*)d_in[11];
    const float* lin2b  = (const float*)d_in[12];
    float* out = (float*)d_out;

    const int* row = ei;
    const int* col = ei + EE;

    void* pv;
    QBuf b0, b1q, b2;
    __half* p_outh; float* p_h;
    cudaGetSymbolAddress(&pv, g_q0);   b0.q  = (int2*)pv;
    cudaGetSymbolAddress(&pv, g_q1);   b1q.q = (int2*)pv;
    cudaGetSymbolAddress(&pv, g_q2);   b2.q  = (int2*)pv;
    cudaGetSymbolAddress(&pv, g_s0);   b0.s  = (__half*)pv;
    cudaGetSymbolAddress(&pv, g_s1);   b1q.s = (__half*)pv;
    cudaGetSymbolAddress(&pv, g_s2);   b2.s  = (__half*)pv;
    cudaGetSymbolAddress(&pv, g_outh); p_outh = (__half*)pv;
    cudaGetSymbolAddress(&pv, g_h);    p_h   = (float*)pv;

    // ---- padded CSR build ----
    init_kernel<<<(NN + 255) / 256, 256>>>();
    count_deg_kernel<<<(EE + 255) / 256, 256>>>(row);
    scan_kernel<<<1, 1024>>>(theta1, thetas);
    scatter_kernel<<<(EE + 255) / 256, 256>>>(row, col);
    pad_fill_kernel<<<(NN + 255) / 256, 256>>>();

    // ---- 3 spectral layers ----
    spectral_layer(x,   128, 0, W1,           b1,       b0, b1q, b2, p_outh, p_h);
    spectral_layer(p_h,  64, 1, Ws,           bs,       b0, b1q, b2, p_outh, p_h);
    spectral_layer(p_h,  64, 2, Ws + 64 * 64, bs + HID, b0, b1q, b2, p_outh, p_h);

    // ---- pool + head ----
    pool_head_kernel<<<NGRAPH, 256>>>(p_h, batch, lin1w, lin1b, lin2w, lin2b, out);
}

// round 9
// speedup vs baseline: 2.0650x; 2.0650x over previous
#include <cuda_runtime.h>
#include <cuda_fp16.h>
#include <mma.h>
#include <math.h>

using namespace nvcuda;

#define NN 100000
#define EE 1600000
#define EPAD (EE + 8 * NN)
#define HID 64
#define KORD 14
#define HEADS 8
#define NGRAPH 128
#define NCLS 10

// ---------------- scratch (device globals; no runtime alloc) ----------------
__device__ __half g_xh  [NN * 128];   // fp16 copy of input features
__device__ __half g_yh  [NN * HID];
__device__ __half g_t1h [NN * HID];
__device__ __half g_t2h [NN * HID];
__device__ __half g_outh[NN * HID];
__device__ __half g_hh  [NN * HID];   // fp16 layer output (GEMM input / pool input)
__device__ int    g_deg[NN];
__device__ float  g_dinv[NN];
__device__ int    g_rowptr[NN + 1];   // padded prefix (multiples of 8)
__device__ int    g_cursor[NN];
__device__ int2   g_edge[EPAD];       // {col, float_bits(weight)}, zero-weight padding
__device__ float  g_coeff[3][KORD];

// ---------------- init ----------------
__global__ void init_kernel() {
    int i = blockIdx.x * blockDim.x + threadIdx.x;
    if (i < NN) { g_deg[i] = 0; g_cursor[i] = 0; }
}

__global__ void count_deg_kernel(const int* __restrict__ row) {
    int e = (blockIdx.x * blockDim.x + threadIdx.x) * 4;
    if (e < EE) {
        int4 r = *(const int4*)(row + e);
        atomicAdd(&g_deg[r.x], 1);
        atomicAdd(&g_deg[r.y], 1);
        atomicAdd(&g_deg[r.z], 1);
        atomicAdd(&g_deg[r.w], 1);
    }
}

// scan (padded degrees) + dinv + coeff fused (single block)
__global__ void scan_kernel(const float* __restrict__ theta1,
                            const float* __restrict__ thetas) {
    __shared__ int sums[1024];
    const int T = 1024;
    int tid = threadIdx.x;

    if (tid < 3 * KORD) {
        int layer = tid / KORD, k = tid % KORD;
        const float* th = (layer == 0) ? theta1 : thetas + (layer - 1) * HEADS * KORD;
        float s = 0.f;
        for (int h = 0; h < HEADS; h++) s += th[h * KORD + k];
        g_coeff[layer][k] = s * (1.0f / HEADS);
    }

    int per = (NN + T - 1) / T;
    int start = tid * per;
    int end = start + per; if (end > NN) end = NN;
    int local = 0;
    for (int i = start; i < end; i++) local += (g_deg[i] + 7) & ~7;
    sums[tid] = local;
    __syncthreads();
    for (int off = 1; off < T; off <<= 1) {
        int t = (tid >= off) ? sums[tid - off] : 0;
        __syncthreads();
        sums[tid] += t;
        __syncthreads();
    }
    int excl = sums[tid] - local;
    int run = excl;
    for (int i = start; i < end; i++) {
        int d = g_deg[i];
        g_rowptr[i] = run; run += (d + 7) & ~7;
        g_dinv[i] = rsqrtf(fmaxf((float)d, 1.0f));
    }
    if (tid == T - 1) g_rowptr[NN] = run;
}

__global__ void scatter_kernel(const int* __restrict__ row, const int* __restrict__ col) {
    int e = (blockIdx.x * blockDim.x + threadIdx.x) * 2;
    if (e < EE) {
        int2 rr = *(const int2*)(row + e);
        int2 cc = *(const int2*)(col + e);
        int pos0 = g_rowptr[rr.x] + atomicAdd(&g_cursor[rr.x], 1);
        g_edge[pos0] = make_int2(cc.x, __float_as_int(-g_dinv[rr.x] * g_dinv[cc.x]));
        int pos1 = g_rowptr[rr.y] + atomicAdd(&g_cursor[rr.y], 1);
        g_edge[pos1] = make_int2(cc.y, __float_as_int(-g_dinv[rr.y] * g_dinv[cc.y]));
    }
}

__global__ void pad_fill_kernel() {
    int r = blockIdx.x * blockDim.x + threadIdx.x;
    if (r < NN) {
        int s = g_rowptr[r] + g_deg[r];
        int e = g_rowptr[r + 1];
        for (int i = s; i < e; i++) g_edge[i] = make_int2(0, 0);
    }
}

// ---------------- x -> fp16 ----------------
__global__ void convert_x_kernel(const float* __restrict__ x, __half* __restrict__ xh) {
    int i = (blockIdx.x * blockDim.x + threadIdx.x) * 4;
    if (i < NN * 128) {
        float4 v = *(const float4*)(x + i);
        __half2 h0 = __floats2half2_rn(v.x, v.y);
        __half2 h1 = __floats2half2_rn(v.z, v.w);
        int2 pk;
        pk.x = *(int*)&h0; pk.y = *(int*)&h1;
        *(int2*)(xh + i) = pk;
    }
}

// ---------------- wmma GEMM: Yh[N][64] = A[N][FIN] @ W[FIN][64] (fp16 in, fp32 acc) ----------------
template <int FIN>
__global__ __launch_bounds__(256) void gemm_wmma_kernel(const __half* __restrict__ A,
                                                        const float* __restrict__ W,
                                                        __half* __restrict__ Yh) {
    __shared__ __half As[128][40];       // 128 rows x 32 k chunk (pad to 40)
    __shared__ __half Ws[32][72];        // 32 k x 64 n (pad to 72)
    __shared__ float  Wb[8][16 * 20];    // per-warp 16x16 staging, ldm 20
    int rowbase = blockIdx.x * 128;
    int tid = threadIdx.x;
    int wid = tid >> 5;
    int lane = tid & 31;

    wmma::fragment<wmma::accumulator, 16, 16, 16, float> acc[4];
#pragma unroll
    for (int i = 0; i < 4; i++) wmma::fill_fragment(acc[i], 0.f);

    for (int kk = 0; kk < FIN; kk += 32) {
        // stage A chunk: 128 rows x 32 halves = 1024 int2; 4 per thread, 8 int2/row
#pragma unroll
        for (int i = 0; i < 4; i++) {
            int j = tid * 4 + i;          // 0..1023
            int r = j >> 3;               // 0..127
            int kq = j & 7;               // 0..7 (int2 within row = 4 halves each)
            int gr = rowbase + r;
            int2 v = make_int2(0, 0);
            if (gr < NN) v = *(const int2*)(A + (size_t)gr * FIN + kk + kq * 4);
            *(int2*)&As[r][kq * 4] = v;
        }
        // stage W chunk: 32 k x 64 n fp32 -> fp16; 512 float4 reads, 2 per thread
#pragma unroll
        for (int i = 0; i < 2; i++) {
            int j = tid * 2 + i;          // 0..511
            int k = j >> 4;               // 0..31
            int nq = j & 15;              // 0..15
            float4 v = *(const float4*)(W + (size_t)(kk + k) * 64 + nq * 4);
            __half2 h0 = __floats2half2_rn(v.x, v.y);
            __half2 h1 = __floats2half2_rn(v.z, v.w);
            int2 pk; pk.x = *(int*)&h0; pk.y = *(int*)&h1;
            *(int2*)&Ws[k][nq * 4] = pk;
        }
        __syncthreads();
#pragma unroll
        for (int ks = 0; ks < 32; ks += 16) {
            wmma::fragment<wmma::matrix_a, 16, 16, 16, __half, wmma::row_major> a_frag;
            wmma::load_matrix_sync(a_frag, &As[wid * 16][ks], 40);
#pragma unroll
            for (int nb = 0; nb < 4; nb++) {
                wmma::fragment<wmma::matrix_b, 16, 16, 16, __half, wmma::row_major> b_frag;
                wmma::load_matrix_sync(b_frag, &Ws[ks][nb * 16], 72);
                wmma::mma_sync(acc[nb], a_frag, b_frag, acc[nb]);
            }
        }
        __syncthreads();
    }
    // epilogue: per-warp staging -> fp16 gmem
#pragma unroll
    for (int nb = 0; nb < 4; nb++) {
        wmma::store_matrix_sync(&Wb[wid][0], acc[nb], 20, wmma::mem_row_major);
        __syncwarp();
        int r = lane >> 1;
        int hc = lane & 1;
        int gr = rowbase + wid * 16 + r;
        if (gr < NN) {
            const float* src = &Wb[wid][r * 20 + hc * 8];
            __half2 o0 = __floats2half2_rn(src[0], src[1]);
            __half2 o1 = __floats2half2_rn(src[2], src[3]);
            __half2 o2 = __floats2half2_rn(src[4], src[5]);
            __half2 o3 = __floats2half2_rn(src[6], src[7]);
            int4 pk;
            pk.x = *(int*)&o0; pk.y = *(int*)&o1;
            pk.z = *(int*)&o2; pk.w = *(int*)&o3;
            *(int4*)(Yh + (size_t)gr * 64 + nb * 16 + hc * 8) = pk;
        }
        __syncwarp();
    }
}

// ---------------- Chebyshev propagation: 8-lane group per row, 8 features/lane ----------------
__device__ __forceinline__ void prop_row8(const int4* __restrict__ t,
                                          int st, int en, int sub, unsigned mask,
                                          float* __restrict__ acc) {
    const int4* tp = t + sub;
#pragma unroll
    for (int i = 0; i < 8; i++) acc[i] = 0.f;
    for (int base = st; base < en; base += 8) {
        int2 ew = __ldg(&g_edge[base + sub]);
        int4 raw[8];
#pragma unroll
        for (int j = 0; j < 8; j++) {
            int cj = __shfl_sync(mask, ew.x, j, 8);
            raw[j] = __ldg(&tp[(size_t)cj * 8]);
        }
#pragma unroll
        for (int j = 0; j < 8; j++) {
            float wj = __int_as_float(__shfl_sync(mask, ew.y, j, 8));
            const __half2* h = (const __half2*)&raw[j];
            float2 f0 = __half22float2(h[0]);
            float2 f1 = __half22float2(h[1]);
            float2 f2 = __half22float2(h[2]);
            float2 f3 = __half22float2(h[3]);
            acc[0] += wj * f0.x; acc[1] += wj * f0.y;
            acc[2] += wj * f1.x; acc[3] += wj * f1.y;
            acc[4] += wj * f2.x; acc[5] += wj * f2.y;
            acc[6] += wj * f3.x; acc[7] += wj * f3.y;
        }
    }
}

__device__ __forceinline__ int4 pack8(const float* v) {
    __half2 h0 = __floats2half2_rn(v[0], v[1]);
    __half2 h1 = __floats2half2_rn(v[2], v[3]);
    __half2 h2 = __floats2half2_rn(v[4], v[5]);
    __half2 h3 = __floats2half2_rn(v[6], v[7]);
    int4 r;
    r.x = *(int*)&h0; r.y = *(int*)&h1;
    r.z = *(int*)&h2; r.w = *(int*)&h3;
    return r;
}

__device__ __forceinline__ void unpack8(int4 raw, float* v) {
    const __half2* h = (const __half2*)&raw;
    float2 f0 = __half22float2(h[0]);
    float2 f1 = __half22float2(h[1]);
    float2 f2 = __half22float2(h[2]);
    float2 f3 = __half22float2(h[3]);
    v[0] = f0.x; v[1] = f0.y; v[2] = f1.x; v[3] = f1.y;
    v[4] = f2.x; v[5] = f2.y; v[6] = f3.x; v[7] = f3.y;
}

// first: t_cur = L~ y ; out = c0*y + c1*t_cur
__global__ __launch_bounds__(256) void cheb_first_kernel(const __half* __restrict__ yh,
                                                         __half* __restrict__ tcur,
                                                         __half* __restrict__ outb,
                                                         int layer) {
    int lane = threadIdx.x & 31;
    int sub = lane & 7;
    int row = blockIdx.x * 32 + (threadIdx.x >> 3);
    if (row >= NN) return;
    unsigned mask = 0xFFu << (lane & 24);
    int s = g_rowptr[row], e = g_rowptr[row + 1];
    float acc[8];
    prop_row8((const int4*)yh, s, e, sub, mask, acc);
    float c0 = g_coeff[layer][0], c1 = g_coeff[layer][1];
    size_t idx = (size_t)row * 8 + sub;
    float yv[8];
    unpack8(((const int4*)yh)[idx], yv);
    ((int4*)tcur)[idx] = pack8(acc);
    float ov[8];
#pragma unroll
    for (int i = 0; i < 8; i++) ov[i] = c0 * yv[i] + c1 * acc[i];
    ((int4*)outb)[idx] = pack8(ov);
}

// step k: t_next = 2*L~ t_cur - t_prev ; out += c_k * t_next
__global__ __launch_bounds__(256) void cheb_step_kernel(const __half* __restrict__ tcur,
                                                        const __half* __restrict__ tprev,
                                                        __half* __restrict__ tnext,
                                                        __half* __restrict__ outb,
                                                        int layer, int k) {
    int lane = threadIdx.x & 31;
    int sub = lane & 7;
    int row = blockIdx.x * 32 + (threadIdx.x >> 3);
    if (row >= NN) return;
    unsigned mask = 0xFFu << (lane & 24);
    int s = g_rowptr[row], e = g_rowptr[row + 1];
    float acc[8];
    prop_row8((const int4*)tcur, s, e, sub, mask, acc);
    size_t idx = (size_t)row * 8 + sub;
    float p[8], tn[8], o[8];
    unpack8(((const int4*)tprev)[idx], p);
#pragma unroll
    for (int i = 0; i < 8; i++) tn[i] = 2.f * acc[i] - p[i];
    ((int4*)tnext)[idx] = pack8(tn);
    float ck = g_coeff[layer][k];
    unpack8(((int4*)outb)[idx], o);
#pragma unroll
    for (int i = 0; i < 8; i++) o[i] += ck * tn[i];
    ((int4*)outb)[idx] = pack8(o);
}

// last step: h_out = relu(out + c_k*(2*L~ t_cur - t_prev) + bias)  (fp16 output)
__global__ __launch_bounds__(256) void cheb_last_kernel(const __half* __restrict__ tcur,
                                                        const __half* __restrict__ tprev,
                                                        const __half* __restrict__ outb,
                                                        const float* __restrict__ bias,
                                                        __half* __restrict__ hout,
                                                        int layer, int k) {
    int lane = threadIdx.x & 31;
    int sub = lane & 7;
    int row = blockIdx.x * 32 + (threadIdx.x >> 3);
    if (row >= NN) return;
    unsigned mask = 0xFFu << (lane & 24);
    int s = g_rowptr[row], e = g_rowptr[row + 1];
    float acc[8];
    prop_row8((const int4*)tcur, s, e, sub, mask, acc);
    size_t idx = (size_t)row * 8 + sub;
    float p[8], o[8];
    unpack8(((const int4*)tprev)[idx], p);
    unpack8(((const int4*)outb)[idx], o);
    float ck = g_coeff[layer][k];
    float4 b0 = *(const float4*)(bias + sub * 8);
    float4 b1 = *(const float4*)(bias + sub * 8 + 4);
    float bb[8] = {b0.x, b0.y, b0.z, b0.w, b1.x, b1.y, b1.z, b1.w};
    float r[8];
#pragma unroll
    for (int i = 0; i < 8; i++) {
        float tni = 2.f * acc[i] - p[i];
        r[i] = fmaxf(o[i] + ck * tni + bb[i], 0.f);
    }
    ((int4*)hout)[idx] = pack8(r);
}

// ---------------- pool (fp16 input) + head + log_softmax ----------------
__global__ __launch_bounds__(256) void pool_head_kernel(const __half* __restrict__ h,
                                                        const int* __restrict__ batch,
                                                        const float* __restrict__ lin1w,
                                                        const float* __restrict__ lin1b,
                                                        const float* __restrict__ lin2w,
                                                        const float* __restrict__ lin2b,
                                                        float* __restrict__ out) {
    int g = blockIdx.x;
    int tid = threadIdx.x;
    int lo = 0, hi = NN;
    while (lo < hi) { int m = (lo + hi) >> 1; if (batch[m] < g) lo = m + 1; else hi = m; }
    int start = lo;
    lo = start; hi = NN;
    while (lo < hi) { int m = (lo + hi) >> 1; if (batch[m] < g + 1) lo = m + 1; else hi = m; }
    int end = lo;

    int f = tid & 63, sub = tid >> 6;
    float acc = 0.f;
    for (int i = start + sub; i < end; i += 4)
        acc += __half2float(h[(size_t)i * HID + f]);
    __shared__ float red[4][64];
    red[sub][f] = acc;
    __syncthreads();
    __shared__ float pooled[64];
    if (tid < 64) {
        float s = red[0][tid] + red[1][tid] + red[2][tid] + red[3][tid];
        float cnt = (float)(end - start);
        pooled[tid] = s / fmaxf(cnt, 1.0f);
    }
    __syncthreads();
    __shared__ float g1[64];
    if (tid < 64) {
        float a = lin1b[tid];
        for (int fk = 0; fk < 64; fk++) a += pooled[fk] * lin1w[fk * 64 + tid];
        g1[tid] = fmaxf(a, 0.f);
    }
    __syncthreads();
    __shared__ float logits[NCLS];
    if (tid < NCLS) {
        float a = lin2b[tid];
        for (int fk = 0; fk < 64; fk++) a += g1[fk] * lin2w[fk * NCLS + tid];
        logits[tid] = a;
    }
    __syncthreads();
    __shared__ float s_lse;
    if (tid == 0) {
        float mx = logits[0];
        for (int c = 1; c < NCLS; c++) mx = fmaxf(mx, logits[c]);
        float s = 0.f;
        for (int c = 0; c < NCLS; c++) s += expf(logits[c] - mx);
        s_lse = mx + logf(s);
    }
    __syncthreads();
    if (tid < NCLS) out[g * NCLS + tid] = logits[tid] - s_lse;
}

// ---------------- host orchestration ----------------
static void spectral_layer(const __half* hin, int fin, int layer,
                           const float* W, const float* bias,
                           __half* p_yh, __half* p_t1h, __half* p_t2h,
                           __half* p_outh, __half* hout) {
    const int CHEB_GRID = (NN + 31) / 32;
    const int GEMM_GRID = (NN + 127) / 128;
    if (fin == 128)
        gemm_wmma_kernel<128><<<GEMM_GRID, 256>>>(hin, W, p_yh);
    else
        gemm_wmma_kernel<64><<<GEMM_GRID, 256>>>(hin, W, p_yh);
    cheb_first_kernel<<<CHEB_GRID, 256>>>(p_yh, p_t1h, p_outh, layer);
    __half* tp = p_yh; __half* tc = p_t1h; __half* tn = p_t2h;
    for (int k = 2; k <= KORD - 2; k++) {
        cheb_step_kernel<<<CHEB_GRID, 256>>>(tc, tp, tn, p_outh, layer, k);
        __half* tmp = tp; tp = tc; tc = tn; tn = tmp;
    }
    cheb_last_kernel<<<CHEB_GRID, 256>>>(tc, tp, p_outh, bias, hout, layer, KORD - 1);
}

extern "C" void kernel_launch(void* const* d_in, const int* in_sizes, int n_in,
                              void* d_out, int out_size) {
    const float* x      = (const float*)d_in[0];
    const int*   ei     = (const int*)d_in[1];
    const int*   batch  = (const int*)d_in[2];
    const float* W1     = (const float*)d_in[3];
    const float* theta1 = (const float*)d_in[4];
    const float* b1     = (const float*)d_in[5];
    const float* Ws     = (const float*)d_in[6];
    const float* thetas = (const float*)d_in[7];
    const float* bs     = (const float*)d_in[8];
    const float* lin1w  = (const float*)d_in[9];
    const float* lin1b  = (const float*)d_in[10];
    const float* lin2w  = (const float*)d_in[11];
    const float* lin2b  = (const float*)d_in[12];
    float* out = (float*)d_out;

    const int* row = ei;
    const int* col = ei + EE;

    void* pv;
    __half *p_xh, *p_yh, *p_t1h, *p_t2h, *p_outh, *p_hh;
    cudaGetSymbolAddress(&pv, g_xh);   p_xh  = (__half*)pv;
    cudaGetSymbolAddress(&pv, g_yh);   p_yh  = (__half*)pv;
    cudaGetSymbolAddress(&pv, g_t1h);  p_t1h = (__half*)pv;
    cudaGetSymbolAddress(&pv, g_t2h);  p_t2h = (__half*)pv;
    cudaGetSymbolAddress(&pv, g_outh); p_outh = (__half*)pv;
    cudaGetSymbolAddress(&pv, g_hh);   p_hh  = (__half*)pv;

    // ---- padded CSR build + x conversion ----
    init_kernel<<<(NN + 255) / 256, 256>>>();
    count_deg_kernel<<<(EE / 4 + 255) / 256, 256>>>(row);
    scan_kernel<<<1, 1024>>>(theta1, thetas);
    scatter_kernel<<<(EE / 2 + 255) / 256, 256>>>(row, col);
    pad_fill_kernel<<<(NN + 255) / 256, 256>>>();
    convert_x_kernel<<<(NN * 128 / 4 + 255) / 256, 256>>>(x, p_xh);

    // ---- 3 spectral layers ----
    spectral_layer(p_xh, 128, 0, W1,           b1,       p_yh, p_t1h, p_t2h, p_outh, p_hh);
    spectral_layer(p_hh,  64, 1, Ws,           bs,       p_yh, p_t1h, p_t2h, p_outh, p_hh);
    spectral_layer(p_hh,  64, 2, Ws + 64 * 64, bs + HID, p_yh, p_t1h, p_t2h, p_outh, p_hh);

    // ---- pool + head ----
    pool_head_kernel<<<NGRAPH, 256>>>(p_hh, batch, lin1w, lin1b, lin2w, lin2b, out);
}